// round 16
// baseline (speedup 1.0000x reference)
#include <cuda_runtime.h>
#include <cuda_fp16.h>
#include <math.h>
#include <stdint.h>

#define NB 8
#define NC 512
#define NL 8192
#define NA 7
#define NPA (NL*NA)
#define PRE_K 600
#define POST_K 100
#define NMW 19
#define LPAD 8194

#define OFF_OBJ  0
#define SZ_OBJ   (NB*NPA)
#define OFF_REG  (SZ_OBJ)
#define SZ_REG   (NB*NPA*2)
#define OFF_ANCH (OFF_REG + SZ_REG)
#define SZ_ANCH  (NPA*2)
#define OFF_PROPS (OFF_ANCH + SZ_ANCH)
#define SZ_PROPS (NB*POST_K*2)
#define OFF_PSC  (OFF_PROPS + SZ_PROPS)
#define OFF_PMASK (OFF_PSC + NB*POST_K)

__device__ float g_pp[(size_t)NB*4*21*NL];
__device__ float g_boxes[(size_t)NB*NPA*2];
__device__ float g_scores[(size_t)NB*NPA];
__device__ int   g_hist[NB*16384];
__device__ unsigned long long g_cand[NB*1024];
__device__ int   g_meta[NB*4];        // [B, ncand, counter, -]
__device__ __align__(256) __half g_fT1[(size_t)NB*LPAD*NC];
__device__ __align__(256) __half g_fT2[(size_t)NB*LPAD*NC];
__device__ __align__(256) __half g_W1[3*512*512];
__device__ __align__(256) __half g_W2[3*512*512];

__constant__ float c_lens[NA] = {1.f,2.f,3.f,4.f,5.f,7.f,9.f};

__device__ __forceinline__ uint32_t smem_u32(const void* p) {
    uint32_t a;
    asm("{ .reg .u64 t; cvta.to.shared.u64 t, %1; cvt.u32.u64 %0, t; }" : "=r"(a) : "l"(p));
    return a;
}
#define CP16(dst,src) asm volatile("cp.async.cg.shared.global [%0], [%1], 16;"::"r"(dst),"l"(src))
#define CPCOMMIT() asm volatile("cp.async.commit_group;":::"memory")
#define CPWAIT1() asm volatile("cp.async.wait_group 1;":::"memory")
#define LDSM4(r,addr) asm volatile( \
    "ldmatrix.sync.aligned.m8n8.x4.shared.b16 {%0,%1,%2,%3}, [%4];" \
    : "=r"((r)[0]),"=r"((r)[1]),"=r"((r)[2]),"=r"((r)[3]) : "r"(addr))
#define MMA(d,a,b0,b1) asm volatile( \
    "mma.sync.aligned.m16n8k16.row.col.f32.f16.f16.f32 " \
    "{%0,%1,%2,%3}, {%4,%5,%6,%7}, {%8,%9}, {%0,%1,%2,%3};" \
    : "+f"((d)[0]),"+f"((d)[1]),"+f"((d)[2]),"+f"((d)[3]) \
    : "r"((a)[0]),"r"((a)[1]),"r"((a)[2]),"r"((a)[3]),"r"(b0),"r"(b1))
#define MMAH(d,a,b0,b1) asm volatile( \
    "mma.sync.aligned.m16n8k16.row.col.f16.f16.f16.f16 " \
    "{%0,%1}, {%2,%3,%4,%5}, {%6,%7}, {%0,%1};" \
    : "+r"((d)[0]),"+r"((d)[1]) \
    : "r"((a)[0]),"r"((a)[1]),"r"((a)[2]),"r"((a)[3]),"r"(b0),"r"(b1))

// ---- prep: weight split + pad rows + hist zero ----
__global__ void splitw_pad_kernel(const float* __restrict__ w) {
    if (blockIdx.x >= 3080) {          // zero histogram: 512 blocks
        int i = (blockIdx.x - 3080)*256 + threadIdx.x;
        if (i < NB*16384) g_hist[i] = 0;
        return;
    }
    if (blockIdx.x >= 3072) {          // pad rows (device globals zero-init; belt+braces)
        int b = blockIdx.x - 3072, c = threadIdx.x;
        __half z = __float2half_rn(0.f);
        size_t r0 = ((size_t)b*LPAD)*NC + 2*c, r1 = ((size_t)b*LPAD + (LPAD-1))*NC + 2*c;
        *(__half2*)(g_fT1+r0) = __halves2half2(z,z); *(__half2*)(g_fT2+r0) = __halves2half2(z,z);
        *(__half2*)(g_fT1+r1) = __halves2half2(z,z); *(__half2*)(g_fT2+r1) = __halves2half2(z,z);
        return;
    }
    int idx = blockIdx.x*256 + threadIdx.x;
    int c = idx & 511, o = (idx >> 9) & 511, t = idx >> 18;
    float v = w[(size_t)o*1536 + c*3 + t];
    __half a1 = __float2half_rn(v);
    g_W1[idx] = a1;
    g_W2[idx] = __float2half_rn(v - __half2float(a1));
}

// ---- feat transpose + 2-limb split ----
__global__ __launch_bounds__(256)
void splitfeat_kernel(const float* __restrict__ feat) {
    __shared__ float tile[64][65];
    int b = blockIdx.z, c0 = blockIdx.y*64, l0 = blockIdx.x*64;
    int tj = threadIdx.x & 63, ti = threadIdx.x >> 6;
    const float* src = feat + ((size_t)b*NC + c0)*NL + l0;
#pragma unroll
    for (int i = ti; i < 64; i += 4) tile[i][tj] = src[(size_t)i*NL + tj];
    __syncthreads();
    int cp = threadIdx.x & 31, li = threadIdx.x >> 5;
#pragma unroll
    for (int lj = li; lj < 64; lj += 8) {
        float v0 = tile[2*cp][lj], v1 = tile[2*cp+1][lj];
        __half a0 = __float2half_rn(v0), a1 = __float2half_rn(v1);
        __half r0 = __float2half_rn(v0 - __half2float(a0));
        __half r1 = __float2half_rn(v1 - __half2float(a1));
        size_t dst = ((size_t)b*LPAD + (l0 + lj + 1))*NC + c0 + 2*cp;
        *(__half2*)(g_fT1 + dst) = __halves2half2(a0, a1);
        *(__half2*)(g_fT2 + dst) = __halves2half2(r0, r1);
    }
}

// ---- conv + fused partial projection (R13/R15 layout, unchanged) ----
#define ROWB2   80u
#define WTILE2  10240u
#define F_OFF2  61440u
#define FTILE2  10560u
#define STG2    82560u
#define CONV_SMEM (2u*STG2)

__device__ __forceinline__ void load_stage(uint32_t sb, int s,
                                           int b, int l0, int o0, int tid) {
    const uint32_t buf = sb + (uint32_t)(s & 1)*STG2;
    const int c0 = s << 5;
#pragma unroll
    for (int i = 0; i < 12; i++) {
        int id = tid + 256*i;
        int r = id & 127, q = (id >> 7) & 3, tl = id >> 9;
        const __half* gw = (tl & 1) ? g_W2 : g_W1;
        size_t src = ((size_t)((tl>>1)*512 + o0 + r))*512 + c0 + q*8;
        CP16(buf + (uint32_t)tl*WTILE2 + (uint32_t)r*ROWB2 + q*16, gw + src);
    }
#pragma unroll
    for (int i = 0; i < 5; i++) {
        int id = tid + 256*i;
        if (id < 1040) {
            int q = id & 3, rem = id >> 2;
            int L = rem >= 130 ? 1 : 0;
            int fr = rem - L*130;
            const __half* gf = L ? g_fT2 : g_fT1;
            size_t src = ((size_t)b*LPAD + (size_t)(l0 + fr))*512 + c0 + q*8;
            CP16(buf + F_OFF2 + (uint32_t)L*FTILE2 + (uint32_t)fr*ROWB2 + q*16, gf + src);
        }
    }
}

__global__ __launch_bounds__(256, 1)
void conv_mma_kernel(const float* __restrict__ bias,
                     const float* __restrict__ obj_w,
                     const float* __restrict__ reg_w) {
    extern __shared__ char smem[];
    uint32_t sb = smem_u32(smem);
    const int tid = threadIdx.x, lane = tid & 31, w = tid >> 5;
    const int wo = w & 1, wl = w >> 1;
    const int b = blockIdx.z, ob = blockIdx.x, o0 = ob*128, l0 = blockIdx.y*128;

    float acc[4][4][4];
    uint32_t acc16[4][4][2];
#pragma unroll
    for (int i=0;i<4;i++)
#pragma unroll
        for (int j=0;j<4;j++) {
#pragma unroll
            for (int k=0;k<4;k++) acc[i][j][k]=0.f;
            acc16[i][j][0]=0u; acc16[i][j][1]=0u;
        }

    load_stage(sb, 0, b, l0, o0, tid); CPCOMMIT();
    load_stage(sb, 1, b, l0, o0, tid); CPCOMMIT();

    const int lr = lane & 15, lc16 = (lane >> 4) * 16;

    for (int s = 0; s < 16; s++) {
        CPWAIT1();
        __syncthreads();
        const uint32_t buf = sb + (uint32_t)(s & 1)*STG2;
#pragma unroll
        for (int t = 0; t < 3; t++) {
#pragma unroll
            for (int kk = 0; kk < 2; kk++) {
                const uint32_t ko = (uint32_t)(kk*32) + lc16;
                uint32_t a1[4][4], a2[4][4], b1[2][4], b2[2][4];
#pragma unroll
                for (int mt = 0; mt < 4; mt++) {
                    uint32_t r = (uint32_t)(wo*64 + mt*16 + lr)*ROWB2 + ko;
                    LDSM4(a1[mt], buf + (uint32_t)(t*2)*WTILE2 + r);
                    LDSM4(a2[mt], buf + (uint32_t)(t*2+1)*WTILE2 + r);
                }
#pragma unroll
                for (int nt = 0; nt < 2; nt++) {
                    uint32_t r = (uint32_t)(wl*32 + nt*16 + lr + t)*ROWB2 + ko;
                    LDSM4(b1[nt], buf + F_OFF2 + r);
                    LDSM4(b2[nt], buf + F_OFF2 + FTILE2 + r);
                }
#pragma unroll
                for (int mt = 0; mt < 4; mt++)
#pragma unroll
                for (int nt = 0; nt < 2; nt++) {
                    MMA(acc[mt][2*nt],   a1[mt], b1[nt][0], b1[nt][2]);
                    MMA(acc[mt][2*nt+1], a1[mt], b1[nt][1], b1[nt][3]);
                }
#pragma unroll
                for (int mt = 0; mt < 4; mt++)
#pragma unroll
                for (int nt = 0; nt < 2; nt++) {
                    MMAH(acc16[mt][2*nt],   a1[mt], b2[nt][0], b2[nt][2]);
                    MMAH(acc16[mt][2*nt+1], a1[mt], b2[nt][1], b2[nt][3]);
                    MMAH(acc16[mt][2*nt],   a2[mt], b1[nt][0], b1[nt][2]);
                    MMAH(acc16[mt][2*nt+1], a2[mt], b1[nt][1], b1[nt][3]);
                }
            }
        }
        __syncthreads();
        if (s + 2 < 16) { load_stage(sb, s+2, b, l0, o0, tid); }
        CPCOMMIT();
    }

    // ---- fused epilogue ----
    __syncthreads();
    float* hs = (float*)smem;                      // [128][132]
    float* w21 = hs + 128*132;                     // [21][128]
    const int r0 = lane >> 2, cp = (lane & 3)*2;
#pragma unroll
    for (int mt = 0; mt < 4; mt++) {
        int orow0 = wo*64 + mt*16 + r0;
        float bv0 = __ldg(bias + o0 + orow0), bv1 = __ldg(bias + o0 + orow0 + 8);
#pragma unroll
        for (int nb = 0; nb < 4; nb++) {
            int lc = wl*32 + nb*8 + cp;
            __half2 x0 = *(__half2*)&acc16[mt][nb][0];
            __half2 x1 = *(__half2*)&acc16[mt][nb][1];
            hs[orow0*132 + lc]       = fmaxf(acc[mt][nb][0] + __half2float(x0.x) + bv0, 0.f);
            hs[orow0*132 + lc + 1]   = fmaxf(acc[mt][nb][1] + __half2float(x0.y) + bv0, 0.f);
            hs[(orow0+8)*132 + lc]   = fmaxf(acc[mt][nb][2] + __half2float(x1.x) + bv1, 0.f);
            hs[(orow0+8)*132 + lc+1] = fmaxf(acc[mt][nb][3] + __half2float(x1.y) + bv1, 0.f);
        }
    }
    for (int i = tid; i < 21*128; i += 256) {
        int a = i >> 7, o = i & 127;
        w21[i] = (a < 7) ? __ldg(obj_w + a*512 + o0 + o)
                         : __ldg(reg_w + (a-7)*512 + o0 + o);
    }
    __syncthreads();

    float* pp = g_pp + (((size_t)b*4 + ob)*21)*NL + l0;
    for (int i = tid; i < 21*32; i += 256) {
        int a = i >> 5, l4 = (i & 31)*4;
        float4 s4 = make_float4(0.f, 0.f, 0.f, 0.f);
        const float* wr = w21 + a*128;
#pragma unroll 8
        for (int o = 0; o < 128; o++) {
            float wv = wr[o];
            float4 h4 = *(float4*)(hs + o*132 + l4);
            s4.x += wv*h4.x; s4.y += wv*h4.y; s4.z += wv*h4.z; s4.w += wv*h4.w;
        }
        *(float4*)(pp + (size_t)a*NL + l4) = s4;
    }
}

// ---- decode: 2 adjacent positions per thread + histogram ----
__global__ __launch_bounds__(256)
void decode_kernel(const float* __restrict__ obj_b,
                   const float* __restrict__ reg_b,
                   float* __restrict__ out) {
    const int b = blockIdx.y;
    const int idx = blockIdx.x*256 + threadIdx.x;   // a*4096 + l/2
    const int a = idx >> 12, l0 = (idx & 4095)*2;
    const float* pb = g_pp + ((size_t)b*4*21)*NL + l0;
    int* hb = g_hist + b*16384;

    float2 so = *(const float2*)(pb + (size_t)a*NL);
    float2 t  = *(const float2*)(pb + (size_t)(21+a)*NL);
    so.x += t.x; so.y += t.y;
    t = *(const float2*)(pb + (size_t)(42+a)*NL); so.x += t.x; so.y += t.y;
    t = *(const float2*)(pb + (size_t)(63+a)*NL); so.x += t.x; so.y += t.y;
    int ra = 7 + 2*a;
    float2 sc_ = *(const float2*)(pb + (size_t)ra*NL);
    t = *(const float2*)(pb + (size_t)(21+ra)*NL); sc_.x += t.x; sc_.y += t.y;
    t = *(const float2*)(pb + (size_t)(42+ra)*NL); sc_.x += t.x; sc_.y += t.y;
    t = *(const float2*)(pb + (size_t)(63+ra)*NL); sc_.x += t.x; sc_.y += t.y;
    float2 sw = *(const float2*)(pb + (size_t)(ra+1)*NL);
    t = *(const float2*)(pb + (size_t)(21+ra+1)*NL); sw.x += t.x; sw.y += t.y;
    t = *(const float2*)(pb + (size_t)(42+ra+1)*NL); sw.x += t.x; sw.y += t.y;
    t = *(const float2*)(pb + (size_t)(63+ra+1)*NL); sw.x += t.x; sw.y += t.y;

    float ob_ = __ldg(obj_b + a);
    float rb0 = __ldg(reg_b + 2*a), rb1 = __ldg(reg_b + 2*a+1);
    float len = c_lens[a];
#pragma unroll
    for (int e = 0; e < 2; e++) {
        int l = l0 + e;
        float ol = (e ? so.y : so.x) + ob_;
        size_t n = (size_t)b*NPA + (size_t)l*NA + a;
        out[OFF_OBJ + n] = ol;
        float scv = 1.f/(1.f + expf(-ol));
        g_scores[n] = scv;
        atomicAdd(&hb[__float_as_uint(scv) >> 16], 1);
        float tc = (e ? sc_.y : sc_.x) + rb0;
        float tw = (e ? sw.y : sw.x) + rb1;
        out[OFF_REG + 2*n] = tc; out[OFF_REG + 2*n+1] = tw;
        float twc = fminf(fmaxf(tw, -10.f), 10.f);
        float cc = ((float)l + 0.5f) + tc*len;
        float ww = len * expf(twc);
        float s = fminf(fmaxf(cc - 0.5f*ww, 0.f), 8192.f);
        float ee = fminf(fmaxf(cc + 0.5f*ww, 0.f), 8192.f);
        ee = fminf(fmaxf(ee, s + 1e-3f), 8192.f);
        s = fmaxf(fminf(s, ee - 1e-3f), 0.f);
        g_boxes[2*n] = s; g_boxes[2*n+1] = ee;
        if (b == 0) {
            float cen = (float)l + 0.5f, half = 0.5f*len;
            size_t m = (size_t)l*NA + a;
            out[OFF_ANCH + 2*m]     = cen - half;
            out[OFF_ANCH + 2*m + 1] = cen + half;
        }
    }
}

// ---- threshold from histogram ----
__global__ __launch_bounds__(512)
void thresh_kernel() {
    __shared__ int csum[512];
    const int b = blockIdx.x, tid = threadIdx.x;
    const int* hist = g_hist + b*16384;
    int cs = 0;
#pragma unroll 8
    for (int j = 0; j < 32; j++) cs += hist[tid*32 + j];
    csum[tid] = cs;
    __syncthreads();
    if (tid == 0) {
        int acc = 0, tc = 511;
        for (; tc > 0; tc--) { if (acc + csum[tc] >= PRE_K) break; acc += csum[tc]; }
        int B = tc*32;
        for (int j = tc*32 + 31; j >= tc*32; j--) {
            if (acc + hist[j] >= PRE_K) { B = j; break; }
            acc += hist[j];
        }
        g_meta[b*4]     = B;
        g_meta[b*4 + 1] = acc + hist[B];
        g_meta[b*4 + 2] = 0;
    }
}

// ---- gridwide candidate compaction ----
__global__ __launch_bounds__(512)
void compact_kernel() {
    const int b = blockIdx.y;
    const int B = g_meta[b*4];
    if (g_meta[b*4 + 1] > 1024) return;     // fallback path handles it
    const float* sc = g_scores + (size_t)b*NPA;
    int p0 = blockIdx.x*7168 + threadIdx.x;
    for (int p = p0; p < blockIdx.x*7168 + 7168; p += 512) {
        unsigned bits = __float_as_uint(sc[p]);
        if ((int)(bits >> 16) >= B) {
            int q = atomicAdd(&g_meta[b*4 + 2], 1);
            g_cand[b*1024 + q] = ((unsigned long long)bits << 32) |
                                 (unsigned long long)(0xFFFFFFFFu - (unsigned)p);
        }
    }
}

// ---- final: sort + NMS + emit ----
#define TK_SMEM 65536
__global__ __launch_bounds__(512)
void topk_nms_kernel(float* __restrict__ out) {
    extern __shared__ char dynsm[];
    unsigned long long* keys = (unsigned long long*)dynsm;    // [1024]
    unsigned* smask = (unsigned*)(dynsm + 8192);              // [PRE_K*NMW]
    int* eqbuf = (int*)(dynsm + 57344);                       // [1024]
    __shared__ float sbox[PRE_K*2];
    __shared__ float ssc[PRE_K];
    __shared__ int skept[POST_K];
    __shared__ int s_cnt, s_g, s_e, s_nk;

    const int b = blockIdx.x, tid = threadIdx.x;
    const float* sc = g_scores + (size_t)b*NPA;
    const int B = g_meta[b*4];
    const int ncand = g_meta[b*4 + 1];

    if (ncand <= 1024) {
        for (int i = tid; i < 1024; i += 512)
            keys[i] = (i < ncand) ? g_cand[b*1024 + i] : 0ULL;
    } else {
        unsigned lo = (unsigned)B << 16, hi = ((unsigned)B << 16) + 0x10000u;
        for (int it = 0; it < 17 && (hi - lo) > 1u; ++it) {
            unsigned mid = lo + ((hi - lo) >> 1);
            if (tid == 0) s_cnt = 0;
            __syncthreads();
            int c = 0;
            for (int p = tid; p < NPA; p += 512)
                c += (__float_as_uint(sc[p]) >= mid) ? 1 : 0;
#pragma unroll
            for (int o = 16; o; o >>= 1) c += __shfl_down_sync(0xffffffffu, c, o);
            if ((tid & 31) == 0) atomicAdd(&s_cnt, c);
            __syncthreads();
            if (s_cnt >= PRE_K) lo = mid; else hi = mid;
            __syncthreads();
        }
        unsigned V = lo;
        if (tid == 0) { s_g = 0; s_e = 0; }
        __syncthreads();
        for (int p = tid; p < NPA; p += 512) {
            unsigned bits = __float_as_uint(sc[p]);
            if (bits > V) {
                int q = atomicAdd(&s_g, 1);
                if (q < 1024)
                    keys[q] = ((unsigned long long)bits << 32) |
                              (unsigned long long)(0xFFFFFFFFu - (unsigned)p);
            } else if (bits == V) {
                int q = atomicAdd(&s_e, 1);
                if (q < 1024) eqbuf[q] = p;
            }
        }
        __syncthreads();
        int ng = s_g < 1024 ? s_g : 1024;
        int ne = s_e < 1024 ? s_e : 1024;
        for (int i = tid; i < 1024; i += 512) {
            if (i >= ng) {
                int e = i - ng;
                keys[i] = (e < ne)
                    ? (((unsigned long long)V << 32) |
                       (unsigned long long)(0xFFFFFFFFu - (unsigned)eqbuf[e]))
                    : 0ULL;
            }
        }
    }

    for (int k = 2; k <= 1024; k <<= 1)
        for (int j = k >> 1; j > 0; j >>= 1) {
            __syncthreads();
            for (int i = tid; i < 1024; i += 512) {
                int l = i ^ j;
                if (l > i) {
                    unsigned long long a = keys[i], bb = keys[l];
                    bool up = ((i & k) == 0);
                    if (up ? (a < bb) : (a > bb)) { keys[i] = bb; keys[l] = a; }
                }
            }
        }
    __syncthreads();

    for (int i = tid; i < PRE_K; i += 512) {
        unsigned long long kv = keys[i];
        unsigned bits = (unsigned)(kv >> 32);
        if (bits == 0u) { ssc[i] = 0.f; sbox[2*i] = 0.f; sbox[2*i+1] = 0.f; }
        else {
            unsigned ridx = 0xFFFFFFFFu - (unsigned)(kv & 0xFFFFFFFFull);
            ssc[i] = __uint_as_float(bits);
            const float* bp = g_boxes + ((size_t)b*NPA + ridx)*2;
            sbox[2*i] = bp[0]; sbox[2*i+1] = bp[1];
        }
    }
    __syncthreads();

    for (int i = tid; i < PRE_K; i += 512) {
        float si = sbox[2*i], ei = sbox[2*i+1], wi = ei - si;
        for (int w = 0; w < NMW; w++) {
            unsigned m = 0;
            int jb = w*32, jm = i - jb; if (jm > 32) jm = 32;
            for (int jj = 0; jj < jm; jj++) {
                int j = jb + jj;
                float sj = sbox[2*j], ej = sbox[2*j+1];
                float inter = fmaxf(fminf(ei, ej) - fmaxf(si, sj), 0.f);
                float iou = inter / fmaxf(wi + (ej - sj) - inter, 1e-6f);
                if (iou > 0.5f) m |= (1u << jj);
            }
            smask[i*NMW + w] = m;
        }
    }
    __syncthreads();

    if (tid < 32) {
        int lane = tid;
        unsigned keepw = 0;
        int nk = 0;
        for (int i = 0; i < PRE_K && nk < POST_K; i++) {
            unsigned mw = (lane < NMW) ? smask[i*NMW + lane] : 0u;
            bool sup = __any_sync(0xffffffffu, (mw & keepw) != 0u);
            bool val = (ssc[i] >= 0.1f);
            if (val && !sup) {
                if (lane == (i >> 5)) keepw |= (1u << (i & 31));
                if (lane == 0) skept[nk] = i;
                nk++;
            }
        }
        if (lane == 0) s_nk = nk;
    }
    __syncthreads();

    int nk = s_nk;
    for (int r = tid; r < POST_K; r += 512) {
        bool on = r < nk;
        int i = on ? skept[r] : 0;
        size_t base = (size_t)b*POST_K + r;
        out[OFF_PROPS + 2*base]   = on ? sbox[2*i]   : 0.f;
        out[OFF_PROPS + 2*base+1] = on ? sbox[2*i+1] : 0.f;
        out[OFF_PSC + base]   = on ? ssc[i] : 0.f;
        out[OFF_PMASK + base] = on ? 1.0f : 0.0f;
    }
}

// ---------------------------------------------------------------------------
extern "C" void kernel_launch(void* const* d_in, const int* in_sizes, int n_in,
                              void* d_out, int out_size) {
    const float* feat   = (const float*)d_in[0];
    const float* conv_w = (const float*)d_in[1];
    const float* conv_b = (const float*)d_in[2];
    const float* obj_w  = (const float*)d_in[3];
    const float* obj_b  = (const float*)d_in[4];
    const float* reg_w  = (const float*)d_in[5];
    const float* reg_b  = (const float*)d_in[6];
    float* out = (float*)d_out;

    cudaFuncSetAttribute(conv_mma_kernel, cudaFuncAttributeMaxDynamicSharedMemorySize, CONV_SMEM);
    cudaFuncSetAttribute(topk_nms_kernel, cudaFuncAttributeMaxDynamicSharedMemorySize, TK_SMEM);

    splitw_pad_kernel<<<3080 + 512, 256>>>(conv_w);
    dim3 sgrid(NL/64, NC/64, NB);
    splitfeat_kernel<<<sgrid, 256>>>(feat);

    dim3 cgrid(4, NL/128, NB);
    conv_mma_kernel<<<cgrid, 256, CONV_SMEM>>>(conv_b, obj_w, reg_w);

    dim3 dgrid((NA*NL/2)/256, NB);           // (112, 8)
    decode_kernel<<<dgrid, 256>>>(obj_b, reg_b, out);

    thresh_kernel<<<NB, 512>>>();
    dim3 kgrid(8, NB);
    compact_kernel<<<kgrid, 512>>>();
    topk_nms_kernel<<<NB, 512, TK_SMEM>>>(out);
}

// round 17
// speedup vs baseline: 1.0231x; 1.0231x over previous
#include <cuda_runtime.h>
#include <cuda_fp16.h>
#include <math.h>
#include <stdint.h>

#define NB 8
#define NC 512
#define NL 8192
#define NA 7
#define NPA (NL*NA)
#define PRE_K 600
#define POST_K 100
#define NMW 19
#define LPAD 8194

#define OFF_OBJ  0
#define SZ_OBJ   (NB*NPA)
#define OFF_REG  (SZ_OBJ)
#define SZ_REG   (NB*NPA*2)
#define OFF_ANCH (OFF_REG + SZ_REG)
#define SZ_ANCH  (NPA*2)
#define OFF_PROPS (OFF_ANCH + SZ_ANCH)
#define SZ_PROPS (NB*POST_K*2)
#define OFF_PSC  (OFF_PROPS + SZ_PROPS)
#define OFF_PMASK (OFF_PSC + NB*POST_K)

__device__ float g_pp[(size_t)NB*4*21*NL];
__device__ float g_boxes[(size_t)NB*NPA*2];
__device__ float g_scores[(size_t)NB*NPA];
__device__ __align__(256) __half g_fT1[(size_t)NB*LPAD*NC];
__device__ __align__(256) __half g_fT2[(size_t)NB*LPAD*NC];
__device__ __align__(256) __half g_W1[3*512*512];
__device__ __align__(256) __half g_W2[3*512*512];

__constant__ float c_lens[NA] = {1.f,2.f,3.f,4.f,5.f,7.f,9.f};

__device__ __forceinline__ uint32_t smem_u32(const void* p) {
    uint32_t a;
    asm("{ .reg .u64 t; cvta.to.shared.u64 t, %1; cvt.u32.u64 %0, t; }" : "=r"(a) : "l"(p));
    return a;
}
#define CP16(dst,src) asm volatile("cp.async.cg.shared.global [%0], [%1], 16;"::"r"(dst),"l"(src))
#define CPCOMMIT() asm volatile("cp.async.commit_group;":::"memory")
#define CPWAIT1() asm volatile("cp.async.wait_group 1;":::"memory")
#define LDSM4(r,addr) asm volatile( \
    "ldmatrix.sync.aligned.m8n8.x4.shared.b16 {%0,%1,%2,%3}, [%4];" \
    : "=r"((r)[0]),"=r"((r)[1]),"=r"((r)[2]),"=r"((r)[3]) : "r"(addr))
#define MMA(d,a,b0,b1) asm volatile( \
    "mma.sync.aligned.m16n8k16.row.col.f32.f16.f16.f32 " \
    "{%0,%1,%2,%3}, {%4,%5,%6,%7}, {%8,%9}, {%0,%1,%2,%3};" \
    : "+f"((d)[0]),"+f"((d)[1]),"+f"((d)[2]),"+f"((d)[3]) \
    : "r"((a)[0]),"r"((a)[1]),"r"((a)[2]),"r"((a)[3]),"r"(b0),"r"(b1))
#define MMAH(d,a,b0,b1) asm volatile( \
    "mma.sync.aligned.m16n8k16.row.col.f16.f16.f16.f16 " \
    "{%0,%1}, {%2,%3,%4,%5}, {%6,%7}, {%0,%1};" \
    : "+r"((d)[0]),"+r"((d)[1]) \
    : "r"((a)[0]),"r"((a)[1]),"r"((a)[2]),"r"((a)[3]),"r"(b0),"r"(b1))

// ---- prep: weight split + pad rows ----
__global__ void splitw_pad_kernel(const float* __restrict__ w) {
    if (blockIdx.x >= 3072) {
        int b = blockIdx.x - 3072, c = threadIdx.x;
        if (c < 512) {
            __half z = __float2half_rn(0.f);
            size_t r0 = ((size_t)b*LPAD)*NC + c, r1 = ((size_t)b*LPAD + (LPAD-1))*NC + c;
            g_fT1[r0]=z; g_fT2[r0]=z;
            g_fT1[r1]=z; g_fT2[r1]=z;
        }
        return;
    }
    int idx = blockIdx.x*256 + threadIdx.x;
    int c = idx & 511, o = (idx >> 9) & 511, t = idx >> 18;
    float v = w[(size_t)o*1536 + c*3 + t];
    __half a1 = __float2half_rn(v);
    g_W1[idx] = a1;
    g_W2[idx] = __float2half_rn(v - __half2float(a1));
}

// ---- feat transpose + 2-limb split, half2 stores ----
__global__ __launch_bounds__(256)
void splitfeat_kernel(const float* __restrict__ feat) {
    __shared__ float tile[64][65];
    int b = blockIdx.z, c0 = blockIdx.y*64, l0 = blockIdx.x*64;
    int tj = threadIdx.x & 63, ti = threadIdx.x >> 6;
    const float* src = feat + ((size_t)b*NC + c0)*NL + l0;
#pragma unroll
    for (int i = ti; i < 64; i += 4) tile[i][tj] = src[(size_t)i*NL + tj];
    __syncthreads();
    int cp = threadIdx.x & 31, li = threadIdx.x >> 5;
#pragma unroll
    for (int lj = li; lj < 64; lj += 8) {
        float v0 = tile[2*cp][lj], v1 = tile[2*cp+1][lj];
        __half a0 = __float2half_rn(v0), a1 = __float2half_rn(v1);
        __half r0 = __float2half_rn(v0 - __half2float(a0));
        __half r1 = __float2half_rn(v1 - __half2float(a1));
        size_t dst = ((size_t)b*LPAD + (l0 + lj + 1))*NC + c0 + 2*cp;
        *(__half2*)(g_fT1 + dst) = __halves2half2(a0, a1);
        *(__half2*)(g_fT2 + dst) = __halves2half2(r0, r1);
    }
}

// ---- conv + fused partial projection ----
#define ROWB2   80u
#define WTILE2  10240u
#define F_OFF2  61440u
#define FTILE2  10560u
#define STG2    82560u
#define CONV_SMEM (2u*STG2)

__device__ __forceinline__ void load_stage(uint32_t sb, int s,
                                           int b, int l0, int o0, int tid) {
    const uint32_t buf = sb + (uint32_t)(s & 1)*STG2;
    const int c0 = s << 5;
#pragma unroll
    for (int i = 0; i < 12; i++) {
        int id = tid + 256*i;
        int r = id & 127, q = (id >> 7) & 3, tl = id >> 9;
        const __half* gw = (tl & 1) ? g_W2 : g_W1;
        size_t src = ((size_t)((tl>>1)*512 + o0 + r))*512 + c0 + q*8;
        CP16(buf + (uint32_t)tl*WTILE2 + (uint32_t)r*ROWB2 + q*16, gw + src);
    }
#pragma unroll
    for (int i = 0; i < 5; i++) {
        int id = tid + 256*i;
        if (id < 1040) {
            int q = id & 3, rem = id >> 2;
            int L = rem >= 130 ? 1 : 0;
            int fr = rem - L*130;
            const __half* gf = L ? g_fT2 : g_fT1;
            size_t src = ((size_t)b*LPAD + (size_t)(l0 + fr))*512 + c0 + q*8;
            CP16(buf + F_OFF2 + (uint32_t)L*FTILE2 + (uint32_t)fr*ROWB2 + q*16, gf + src);
        }
    }
}

__global__ __launch_bounds__(256, 1)
void conv_mma_kernel(const float* __restrict__ bias,
                     const float* __restrict__ obj_w,
                     const float* __restrict__ reg_w) {
    extern __shared__ char smem[];
    uint32_t sb = smem_u32(smem);
    const int tid = threadIdx.x, lane = tid & 31, w = tid >> 5;
    const int wo = w & 1, wl = w >> 1;
    const int b = blockIdx.z, ob = blockIdx.x, o0 = ob*128, l0 = blockIdx.y*128;

    float acc[4][4][4];
    uint32_t acc16[4][4][2];
#pragma unroll
    for (int i=0;i<4;i++)
#pragma unroll
        for (int j=0;j<4;j++) {
#pragma unroll
            for (int k=0;k<4;k++) acc[i][j][k]=0.f;
            acc16[i][j][0]=0u; acc16[i][j][1]=0u;
        }

    load_stage(sb, 0, b, l0, o0, tid); CPCOMMIT();
    load_stage(sb, 1, b, l0, o0, tid); CPCOMMIT();

    const int lr = lane & 15, lc16 = (lane >> 4) * 16;

    for (int s = 0; s < 16; s++) {
        CPWAIT1();
        __syncthreads();
        const uint32_t buf = sb + (uint32_t)(s & 1)*STG2;
#pragma unroll
        for (int t = 0; t < 3; t++) {
#pragma unroll
            for (int kk = 0; kk < 2; kk++) {
                const uint32_t ko = (uint32_t)(kk*32) + lc16;
                uint32_t a1[4][4], a2[4][4], b1[2][4], b2[2][4];
#pragma unroll
                for (int mt = 0; mt < 4; mt++) {
                    uint32_t r = (uint32_t)(wo*64 + mt*16 + lr)*ROWB2 + ko;
                    LDSM4(a1[mt], buf + (uint32_t)(t*2)*WTILE2 + r);
                    LDSM4(a2[mt], buf + (uint32_t)(t*2+1)*WTILE2 + r);
                }
#pragma unroll
                for (int nt = 0; nt < 2; nt++) {
                    uint32_t r = (uint32_t)(wl*32 + nt*16 + lr + t)*ROWB2 + ko;
                    LDSM4(b1[nt], buf + F_OFF2 + r);
                    LDSM4(b2[nt], buf + F_OFF2 + FTILE2 + r);
                }
#pragma unroll
                for (int mt = 0; mt < 4; mt++)
#pragma unroll
                for (int nt = 0; nt < 2; nt++) {
                    MMA(acc[mt][2*nt],   a1[mt], b1[nt][0], b1[nt][2]);
                    MMA(acc[mt][2*nt+1], a1[mt], b1[nt][1], b1[nt][3]);
                }
#pragma unroll
                for (int mt = 0; mt < 4; mt++)
#pragma unroll
                for (int nt = 0; nt < 2; nt++) {
                    MMAH(acc16[mt][2*nt],   a1[mt], b2[nt][0], b2[nt][2]);
                    MMAH(acc16[mt][2*nt+1], a1[mt], b2[nt][1], b2[nt][3]);
                    MMAH(acc16[mt][2*nt],   a2[mt], b1[nt][0], b1[nt][2]);
                    MMAH(acc16[mt][2*nt+1], a2[mt], b1[nt][1], b1[nt][3]);
                }
            }
        }
        __syncthreads();
        if (s + 2 < 16) { load_stage(sb, s+2, b, l0, o0, tid); }
        CPCOMMIT();
    }

    // ---- fused epilogue ----
    __syncthreads();
    float* hs = (float*)smem;                      // [128][132]
    float* w21 = hs + 128*132;                     // [21][128]
    const int r0 = lane >> 2, cp = (lane & 3)*2;
#pragma unroll
    for (int mt = 0; mt < 4; mt++) {
        int orow0 = wo*64 + mt*16 + r0;
        float bv0 = __ldg(bias + o0 + orow0), bv1 = __ldg(bias + o0 + orow0 + 8);
#pragma unroll
        for (int nb = 0; nb < 4; nb++) {
            int lc = wl*32 + nb*8 + cp;
            __half2 x0 = *(__half2*)&acc16[mt][nb][0];
            __half2 x1 = *(__half2*)&acc16[mt][nb][1];
            hs[orow0*132 + lc]       = fmaxf(acc[mt][nb][0] + __half2float(x0.x) + bv0, 0.f);
            hs[orow0*132 + lc + 1]   = fmaxf(acc[mt][nb][1] + __half2float(x0.y) + bv0, 0.f);
            hs[(orow0+8)*132 + lc]   = fmaxf(acc[mt][nb][2] + __half2float(x1.x) + bv1, 0.f);
            hs[(orow0+8)*132 + lc+1] = fmaxf(acc[mt][nb][3] + __half2float(x1.y) + bv1, 0.f);
        }
    }
    for (int i = tid; i < 21*128; i += 256) {
        int a = i >> 7, o = i & 127;
        w21[i] = (a < 7) ? __ldg(obj_w + a*512 + o0 + o)
                         : __ldg(reg_w + (a-7)*512 + o0 + o);
    }
    __syncthreads();

    float* pp = g_pp + (((size_t)b*4 + ob)*21)*NL + l0;
    for (int i = tid; i < 21*32; i += 256) {
        int a = i >> 5, l4 = (i & 31)*4;
        float4 s4 = make_float4(0.f, 0.f, 0.f, 0.f);
        const float* wr = w21 + a*128;
#pragma unroll 8
        for (int o = 0; o < 128; o++) {
            float wv = wr[o];
            float4 h4 = *(float4*)(hs + o*132 + l4);
            s4.x += wv*h4.x; s4.y += wv*h4.y; s4.z += wv*h4.z; s4.w += wv*h4.w;
        }
        *(float4*)(pp + (size_t)a*NL + l4) = s4;
    }
}

// ---- decode: one thread per (l, a) ----
__global__ __launch_bounds__(256)
void decode_kernel(const float* __restrict__ obj_b,
                   const float* __restrict__ reg_b,
                   float* __restrict__ out) {
    const int b = blockIdx.y;
    const int idx = blockIdx.x*256 + threadIdx.x;
    const int a = idx >> 13, l = idx & (NL-1);
    const float* pb = g_pp + ((size_t)b*4*21)*NL + l;

    float s_obj = __ldg(pb + (size_t)a*NL) + __ldg(pb + (size_t)(21+a)*NL)
                + __ldg(pb + (size_t)(42+a)*NL) + __ldg(pb + (size_t)(63+a)*NL);
    int ra = 7 + 2*a;
    float t_c = __ldg(pb + (size_t)ra*NL) + __ldg(pb + (size_t)(21+ra)*NL)
              + __ldg(pb + (size_t)(42+ra)*NL) + __ldg(pb + (size_t)(63+ra)*NL);
    float t_w = __ldg(pb + (size_t)(ra+1)*NL) + __ldg(pb + (size_t)(21+ra+1)*NL)
              + __ldg(pb + (size_t)(42+ra+1)*NL) + __ldg(pb + (size_t)(63+ra+1)*NL);

    float ol = s_obj + __ldg(obj_b + a);
    size_t n = (size_t)b*NPA + (size_t)l*NA + a;
    out[OFF_OBJ + n] = ol;
    g_scores[n] = 1.f/(1.f + expf(-ol));
    float tc = t_c + __ldg(reg_b + 2*a);
    float tw = t_w + __ldg(reg_b + 2*a+1);
    out[OFF_REG + 2*n] = tc; out[OFF_REG + 2*n+1] = tw;
    float len = c_lens[a];
    float twc = fminf(fmaxf(tw, -10.f), 10.f);
    float cc = ((float)l + 0.5f) + tc*len;
    float ww = len * expf(twc);
    float s = fminf(fmaxf(cc - 0.5f*ww, 0.f), 8192.f);
    float e = fminf(fmaxf(cc + 0.5f*ww, 0.f), 8192.f);
    e = fminf(fmaxf(e, s + 1e-3f), 8192.f);
    s = fmaxf(fminf(s, e - 1e-3f), 0.f);
    g_boxes[2*n] = s; g_boxes[2*n+1] = e;
    if (b == 0) {
        float cen = (float)l + 0.5f, half = 0.5f*len;
        size_t m = (size_t)l*NA + a;
        out[OFF_ANCH + 2*m]     = cen - half;
        out[OFF_ANCH + 2*m + 1] = cen + half;
    }
}

// ---- topk + NMS (R15 form; balanced mask rows) ----
#define TK_SMEM 65536
__global__ __launch_bounds__(512)
void topk_nms_kernel(float* __restrict__ out) {
    extern __shared__ char dynsm[];
    int* hist = (int*)dynsm;
    unsigned long long* keys = (unsigned long long*)dynsm;
    unsigned* smask = (unsigned*)(dynsm + 8192);
    int* eqbuf = (int*)(dynsm + 57344);
    __shared__ float sbox[PRE_K*2];
    __shared__ float ssc[PRE_K];
    __shared__ int skept[POST_K];
    __shared__ int csum[512];
    __shared__ int s_cnt, s_g, s_e, s_nk, s_B, s_ncand;

    const int b = blockIdx.x, tid = threadIdx.x;
    const float* sc = g_scores + (size_t)b*NPA;

    for (int i = tid; i < 16384; i += 512) hist[i] = 0;
    __syncthreads();
    for (int p = tid; p < NPA; p += 512)
        atomicAdd(&hist[__float_as_uint(sc[p]) >> 16], 1);
    __syncthreads();
    int cs = 0;
#pragma unroll 8
    for (int j = 0; j < 32; j++) cs += hist[tid*32 + j];
    csum[tid] = cs;
    __syncthreads();
    if (tid == 0) {
        int acc = 0, tc = 511;
        for (; tc > 0; tc--) { if (acc + csum[tc] >= PRE_K) break; acc += csum[tc]; }
        int B = tc*32;
        for (int j = tc*32 + 31; j >= tc*32; j--) {
            if (acc + hist[j] >= PRE_K) { B = j; break; }
            acc += hist[j];
        }
        s_B = B; s_ncand = acc + hist[B];
    }
    __syncthreads();
    const int B = s_B;
    const int ncand = s_ncand;

    if (ncand <= 1024) {
        if (tid == 0) s_g = 0;
        __syncthreads();
        for (int p = tid; p < NPA; p += 512) {
            unsigned bits = __float_as_uint(sc[p]);
            if ((int)(bits >> 16) >= B) {
                int q = atomicAdd(&s_g, 1);
                keys[q] = ((unsigned long long)bits << 32) |
                          (unsigned long long)(0xFFFFFFFFu - (unsigned)p);
            }
        }
        __syncthreads();
        for (int i = tid + ncand; i < 1024; i += 512) keys[i] = 0ULL;
    } else {
        unsigned lo = (unsigned)B << 16, hi = ((unsigned)B << 16) + 0x10000u;
        for (int it = 0; it < 17 && (hi - lo) > 1u; ++it) {
            unsigned mid = lo + ((hi - lo) >> 1);
            if (tid == 0) s_cnt = 0;
            __syncthreads();
            int c = 0;
            for (int p = tid; p < NPA; p += 512)
                c += (__float_as_uint(sc[p]) >= mid) ? 1 : 0;
#pragma unroll
            for (int o = 16; o; o >>= 1) c += __shfl_down_sync(0xffffffffu, c, o);
            if ((tid & 31) == 0) atomicAdd(&s_cnt, c);
            __syncthreads();
            if (s_cnt >= PRE_K) lo = mid; else hi = mid;
            __syncthreads();
        }
        unsigned V = lo;
        if (tid == 0) { s_g = 0; s_e = 0; }
        __syncthreads();
        for (int p = tid; p < NPA; p += 512) {
            unsigned bits = __float_as_uint(sc[p]);
            if (bits > V) {
                int q = atomicAdd(&s_g, 1);
                if (q < 1024)
                    keys[q] = ((unsigned long long)bits << 32) |
                              (unsigned long long)(0xFFFFFFFFu - (unsigned)p);
            } else if (bits == V) {
                int q = atomicAdd(&s_e, 1);
                if (q < 1024) eqbuf[q] = p;
            }
        }
        __syncthreads();
        int ng = s_g < 1024 ? s_g : 1024;
        int ne = s_e < 1024 ? s_e : 1024;
        for (int i = tid; i < 1024; i += 512) {
            if (i >= ng) {
                int e = i - ng;
                keys[i] = (e < ne)
                    ? (((unsigned long long)V << 32) |
                       (unsigned long long)(0xFFFFFFFFu - (unsigned)eqbuf[e]))
                    : 0ULL;
            }
        }
    }

    for (int k = 2; k <= 1024; k <<= 1)
        for (int j = k >> 1; j > 0; j >>= 1) {
            __syncthreads();
            for (int i = tid; i < 1024; i += 512) {
                int l = i ^ j;
                if (l > i) {
                    unsigned long long a = keys[i], bb = keys[l];
                    bool up = ((i & k) == 0);
                    if (up ? (a < bb) : (a > bb)) { keys[i] = bb; keys[l] = a; }
                }
            }
        }
    __syncthreads();

    for (int i = tid; i < PRE_K; i += 512) {
        unsigned long long kv = keys[i];
        unsigned bits = (unsigned)(kv >> 32);
        if (bits == 0u) { ssc[i] = 0.f; sbox[2*i] = 0.f; sbox[2*i+1] = 0.f; }
        else {
            unsigned ridx = 0xFFFFFFFFu - (unsigned)(kv & 0xFFFFFFFFull);
            ssc[i] = __uint_as_float(bits);
            const float* bp = g_boxes + ((size_t)b*NPA + ridx)*2;
            sbox[2*i] = bp[0]; sbox[2*i+1] = bp[1];
        }
    }
    __syncthreads();

    // balanced rows: thread handles i and PRE_K-1-i
    for (int ii = tid; ii < PRE_K; ii += 512) {
        int i = (ii < 300) ? ii : (PRE_K - 1 - (ii - 300));
        float si = sbox[2*i], ei = sbox[2*i+1], wi = ei - si;
        for (int w = 0; w < NMW; w++) {
            unsigned m = 0;
            int jb = w*32, jm = i - jb; if (jm > 32) jm = 32;
            for (int jj = 0; jj < jm; jj++) {
                int j = jb + jj;
                float sj = sbox[2*j], ej = sbox[2*j+1];
                float inter = fmaxf(fminf(ei, ej) - fmaxf(si, sj), 0.f);
                float iou = inter / fmaxf(wi + (ej - sj) - inter, 1e-6f);
                if (iou > 0.5f) m |= (1u << jj);
            }
            smask[i*NMW + w] = m;
        }
    }
    __syncthreads();

    if (tid < 32) {
        int lane = tid;
        unsigned keepw = 0;
        int nk = 0;
        for (int i = 0; i < PRE_K && nk < POST_K; i++) {
            unsigned mw = (lane < NMW) ? smask[i*NMW + lane] : 0u;
            bool sup = __any_sync(0xffffffffu, (mw & keepw) != 0u);
            bool val = (ssc[i] >= 0.1f);
            if (val && !sup) {
                if (lane == (i >> 5)) keepw |= (1u << (i & 31));
                if (lane == 0) skept[nk] = i;
                nk++;
            }
        }
        if (lane == 0) s_nk = nk;
    }
    __syncthreads();

    int nk = s_nk;
    for (int r = tid; r < POST_K; r += 512) {
        bool on = r < nk;
        int i = on ? skept[r] : 0;
        size_t base = (size_t)b*POST_K + r;
        out[OFF_PROPS + 2*base]   = on ? sbox[2*i]   : 0.f;
        out[OFF_PROPS + 2*base+1] = on ? sbox[2*i+1] : 0.f;
        out[OFF_PSC + base]   = on ? ssc[i] : 0.f;
        out[OFF_PMASK + base] = on ? 1.0f : 0.0f;
    }
}

// ---------------------------------------------------------------------------
extern "C" void kernel_launch(void* const* d_in, const int* in_sizes, int n_in,
                              void* d_out, int out_size) {
    const float* feat   = (const float*)d_in[0];
    const float* conv_w = (const float*)d_in[1];
    const float* conv_b = (const float*)d_in[2];
    const float* obj_w  = (const float*)d_in[3];
    const float* obj_b  = (const float*)d_in[4];
    const float* reg_w  = (const float*)d_in[5];
    const float* reg_b  = (const float*)d_in[6];
    float* out = (float*)d_out;

    cudaFuncSetAttribute(conv_mma_kernel, cudaFuncAttributeMaxDynamicSharedMemorySize, CONV_SMEM);
    cudaFuncSetAttribute(topk_nms_kernel, cudaFuncAttributeMaxDynamicSharedMemorySize, TK_SMEM);

    splitw_pad_kernel<<<3072 + NB, 256>>>(conv_w);
    dim3 sgrid(NL/64, NC/64, NB);
    splitfeat_kernel<<<sgrid, 256>>>(feat);

    dim3 cgrid(4, NL/128, NB);
    conv_mma_kernel<<<cgrid, 256, CONV_SMEM>>>(conv_b, obj_w, reg_w);

    dim3 dgrid((NA*NL)/256, NB);
    decode_kernel<<<dgrid, 256>>>(obj_b, reg_b, out);

    topk_nms_kernel<<<NB, 512, TK_SMEM>>>(out);
}